// round 3
// baseline (speedup 1.0000x reference)
#include <cuda_runtime.h>
#include <cuda_bf16.h>

// D=128, N=500000, P=1024, K=32
// loss = -0.5 * sum_j dot(U[:,seg_ids[j]], U_base[:,merge_idx[j]])^2
//        -0.5 * mean( (U^T U)[G]^2 )
// Gram trick: rowsq[r] = sum_q (u_r . u_q)^2 = u_r^T (U U^T) u_r, M = U U^T [DxD]
// NOTE: JAX x64 is disabled by default, so the "int64" index arrays are int32.

#define D_DIM 128

__device__ float g_M[D_DIM * D_DIM];      // U U^T
__device__ float g_rowsq[4096];           // rowsq per gram row (P <= 4096)

// ---------------------------------------------------------------------------
// Kernel 1: M = U U^T  (D x D, inner dim P), also zeroes the output scalar.
// ---------------------------------------------------------------------------
__global__ void compute_M_kernel(const float* __restrict__ U, int P, float* __restrict__ out)
{
    __shared__ float As[32][33];
    __shared__ float Bs[32][33];

    if (blockIdx.x == 0 && blockIdx.y == 0 && threadIdx.x == 0 && threadIdx.y == 0)
        out[0] = 0.0f;

    const int tx = threadIdx.x;
    const int ty = threadIdx.y;
    const int row = blockIdx.y * 32 + ty;
    const int col = blockIdx.x * 32 + tx;

    float acc = 0.0f;
    for (int q0 = 0; q0 < P; q0 += 32) {
        As[ty][tx] = U[(blockIdx.y * 32 + ty) * P + q0 + tx];
        Bs[ty][tx] = U[(blockIdx.x * 32 + ty) * P + q0 + tx];
        __syncthreads();
        #pragma unroll
        for (int t = 0; t < 32; ++t)
            acc += As[ty][t] * Bs[tx][t];
        __syncthreads();
    }
    g_M[row * D_DIM + col] = acc;
}

// ---------------------------------------------------------------------------
// Kernel 2: rowsq[r] = u_r^T M u_r, u_r = column r of U. One 128-thread block per r.
// ---------------------------------------------------------------------------
__global__ void rowsq_kernel(const float* __restrict__ U, int P)
{
    const int r = blockIdx.x;
    const int d = threadIdx.x;    // 0..127

    __shared__ float u[D_DIM];
    u[d] = U[d * P + r];
    __syncthreads();

    const float* Mrow = g_M + d * D_DIM;
    float t = 0.0f;
    #pragma unroll 16
    for (int e = 0; e < D_DIM; ++e)
        t += Mrow[e] * u[e];

    float val = t * u[d];

    #pragma unroll
    for (int off = 16; off > 0; off >>= 1)
        val += __shfl_down_sync(0xffffffffu, val, off);

    __shared__ float wsum[4];
    if ((d & 31) == 0) wsum[d >> 5] = val;
    __syncthreads();
    if (d == 0)
        g_rowsq[r] = wsum[0] + wsum[1] + wsum[2] + wsum[3];
}

// ---------------------------------------------------------------------------
// Kernel 3: out += -0.5/(P*K*P) * sum_{p,k} rowsq[G[p,k]]   (G is int32)
// ---------------------------------------------------------------------------
__global__ void gather_kernel(const int* __restrict__ G, int nG, float coef,
                              float* __restrict__ out)
{
    int i = blockIdx.x * blockDim.x + threadIdx.x;
    float val = 0.0f;
    for (; i < nG; i += gridDim.x * blockDim.x)
        val += g_rowsq[G[i]];

    #pragma unroll
    for (int off = 16; off > 0; off >>= 1)
        val += __shfl_down_sync(0xffffffffu, val, off);

    __shared__ float wsum[32];
    const int lane = threadIdx.x & 31, wid = threadIdx.x >> 5;
    if (lane == 0) wsum[wid] = val;
    __syncthreads();
    if (wid == 0) {
        const int nw = blockDim.x >> 5;
        float v = (lane < nw) ? wsum[lane] : 0.0f;
        #pragma unroll
        for (int off = 16; off > 0; off >>= 1)
            v += __shfl_down_sync(0xffffffffu, v, off);
        if (lane == 0) atomicAdd(out, coef * v);
    }
}

// ---------------------------------------------------------------------------
// Kernel 4 (dominant, HBM-bound): per column j,
//   dot = sum_d U_base[d*N + merge_idx[j]] * U[d*P + seg_ids[j]]
//   out += -0.5 * dot^2   (block-reduced partials, then one atomic per block)
// Indices are int32.
// ---------------------------------------------------------------------------
__global__ void __launch_bounds__(256) dots_kernel(
    const float* __restrict__ U_base,
    const float* __restrict__ U,
    const int* __restrict__ merge_idx,
    const int* __restrict__ seg_ids,
    int N, int P, float* __restrict__ out)
{
    const int j = blockIdx.x * blockDim.x + threadIdx.x;

    float partial = 0.0f;
    if (j < N) {
        const int mi = merge_idx[j];
        const int g  = seg_ids[j];
        const float* ub = U_base + mi;
        const float* uu = U + g;

        float a0 = 0.f, a1 = 0.f, a2 = 0.f, a3 = 0.f;
        #pragma unroll
        for (int d = 0; d < D_DIM; d += 4) {
            a0 += ub[(long long)(d + 0) * N] * uu[(d + 0) * P];
            a1 += ub[(long long)(d + 1) * N] * uu[(d + 1) * P];
            a2 += ub[(long long)(d + 2) * N] * uu[(d + 2) * P];
            a3 += ub[(long long)(d + 3) * N] * uu[(d + 3) * P];
        }
        const float dot = (a0 + a1) + (a2 + a3);
        partial = -0.5f * dot * dot;
    }

    #pragma unroll
    for (int off = 16; off > 0; off >>= 1)
        partial += __shfl_down_sync(0xffffffffu, partial, off);

    __shared__ float wsum[8];
    const int lane = threadIdx.x & 31, wid = threadIdx.x >> 5;
    if (lane == 0) wsum[wid] = partial;
    __syncthreads();
    if (wid == 0) {
        float v = (lane < 8) ? wsum[lane] : 0.0f;
        #pragma unroll
        for (int off = 4; off > 0; off >>= 1)
            v += __shfl_down_sync(0xffffffffu, v, off);
        if (lane == 0) atomicAdd(out, v);
    }
}

// ---------------------------------------------------------------------------
extern "C" void kernel_launch(void* const* d_in, const int* in_sizes, int n_in,
                              void* d_out, int out_size)
{
    const float* U_base    = (const float*)d_in[0];
    const float* U         = (const float*)d_in[1];
    const int*   merge_idx = (const int*)d_in[2];
    const int*   seg_ids   = (const int*)d_in[3];
    const int*   G         = (const int*)d_in[4];
    float* out = (float*)d_out;

    const int N  = in_sizes[2];                 // 500000
    const int P  = in_sizes[1] / D_DIM;         // 1024
    const int nG = in_sizes[4];                 // P*K = 32768
    const int K  = nG / P;                      // 32

    // 1) M = U U^T (also zeroes out[0])
    {
        dim3 blk(32, 32);
        dim3 grd(D_DIM / 32, D_DIM / 32);
        compute_M_kernel<<<grd, blk>>>(U, P, out);
    }
    // 2) rowsq[r] = u_r^T M u_r
    rowsq_kernel<<<P, D_DIM>>>(U, P);
    // 3) gram gather term
    {
        const float coef = -0.5f / ((float)P * (float)K * (float)P);
        gather_kernel<<<32, 256>>>(G, nG, coef, out);
    }
    // 4) main ragged-dot term (HBM-bound)
    {
        const int threads = 256;
        const int blocks = (N + threads - 1) / threads;
        dots_kernel<<<blocks, threads>>>(U_base, U, merge_idx, seg_ids, N, P, out);
    }
}

// round 4
// speedup vs baseline: 1.0303x; 1.0303x over previous
#include <cuda_runtime.h>
#include <cuda_bf16.h>

// D=128, N=500000, P=1024, K=32 (indices are int32: JAX x64 disabled)
// loss = -0.5 * sum_j dot(U[:,seg_ids[j]], U_base[:,merge_idx[j]])^2
//        -0.5 * mean( (U^T U)[G]^2 )
// Gram: rowsq[r] = u_r^T (U U^T) u_r = sum_d (M U)[d,r] * U[d,r],  M = U U^T

#define D_DIM 128
#define P_MAX 4096

__device__ float g_M[D_DIM * D_DIM];       // U U^T              [D,D]
__device__ float g_W[D_DIM * P_MAX];       // M @ U              [D,P]
__device__ float g_rowsq[P_MAX];           // diag(U^T M U)      [P]

// ---------------------------------------------------------------------------
// Kernel 1: M = U U^T (inner dim P). Also zeroes the output scalar.
// ---------------------------------------------------------------------------
__global__ void compute_M_kernel(const float* __restrict__ U, int P, float* __restrict__ out)
{
    __shared__ float As[32][33];
    __shared__ float Bs[32][33];

    if (blockIdx.x == 0 && blockIdx.y == 0 && threadIdx.x == 0 && threadIdx.y == 0)
        out[0] = 0.0f;

    const int tx = threadIdx.x, ty = threadIdx.y;
    const int row = blockIdx.y * 32 + ty;
    const int col = blockIdx.x * 32 + tx;

    float acc = 0.0f;
    for (int q0 = 0; q0 < P; q0 += 32) {
        As[ty][tx] = U[(blockIdx.y * 32 + ty) * P + q0 + tx];
        Bs[ty][tx] = U[(blockIdx.x * 32 + ty) * P + q0 + tx];
        __syncthreads();
        #pragma unroll
        for (int t = 0; t < 32; ++t)
            acc += As[ty][t] * Bs[tx][t];
        __syncthreads();
    }
    g_M[row * D_DIM + col] = acc;
}

// ---------------------------------------------------------------------------
// Kernel 2a: W = M @ U   (D x P, inner dim D). Tiled 32x32.
// grid = (P/32, D/32), block = (32,32)
// ---------------------------------------------------------------------------
__global__ void compute_W_kernel(const float* __restrict__ U, int P)
{
    __shared__ float Ms[32][33];
    __shared__ float Us[32][33];

    const int tx = threadIdx.x, ty = threadIdx.y;
    const int row = blockIdx.y * 32 + ty;   // d
    const int col = blockIdx.x * 32 + tx;   // c

    float acc = 0.0f;
    #pragma unroll
    for (int e0 = 0; e0 < D_DIM; e0 += 32) {
        Ms[ty][tx] = g_M[row * D_DIM + e0 + tx];
        Us[ty][tx] = U[(e0 + ty) * P + col];
        __syncthreads();
        #pragma unroll
        for (int t = 0; t < 32; ++t)
            acc += Ms[ty][t] * Us[t][tx];
        __syncthreads();
    }
    g_W[row * P + col] = acc;
}

// ---------------------------------------------------------------------------
// Kernel 2b: rowsq[c] = sum_d W[d,c] * U[d,c].  Coalesced over c.
// ---------------------------------------------------------------------------
__global__ void rowsq_reduce_kernel(const float* __restrict__ U, int P)
{
    const int c = blockIdx.x * blockDim.x + threadIdx.x;
    if (c >= P) return;
    float acc = 0.0f;
    #pragma unroll 8
    for (int d = 0; d < D_DIM; ++d)
        acc += g_W[d * P + c] * U[d * P + c];
    g_rowsq[c] = acc;
}

// ---------------------------------------------------------------------------
// Kernel 3: out += -0.5/(P*K*P) * sum rowsq[G[i]]
// ---------------------------------------------------------------------------
__global__ void gather_kernel(const int* __restrict__ G, int nG, float coef,
                              float* __restrict__ out)
{
    int i = blockIdx.x * blockDim.x + threadIdx.x;
    float val = 0.0f;
    for (; i < nG; i += gridDim.x * blockDim.x)
        val += g_rowsq[G[i]];

    #pragma unroll
    for (int off = 16; off > 0; off >>= 1)
        val += __shfl_down_sync(0xffffffffu, val, off);

    __shared__ float wsum[8];
    const int lane = threadIdx.x & 31, wid = threadIdx.x >> 5;
    if (lane == 0) wsum[wid] = val;
    __syncthreads();
    if (wid == 0) {
        const int nw = blockDim.x >> 5;
        float v = (lane < nw) ? wsum[lane] : 0.0f;
        #pragma unroll
        for (int off = 4; off > 0; off >>= 1)
            v += __shfl_down_sync(0xffffffffu, v, off);
        if (lane == 0) atomicAdd(out, coef * v);
    }
}

// ---------------------------------------------------------------------------
// Kernel 4 (dominant, HBM-bound). Two columns j per thread for 2x MLP.
//   dot_j = sum_d U_base[d*N + merge_idx[j]] * U[d*P + seg_ids[j]]
//   out  += -0.5 * dot_j^2
// ---------------------------------------------------------------------------
__global__ void __launch_bounds__(256) dots_kernel(
    const float* __restrict__ U_base,
    const float* __restrict__ U,
    const int* __restrict__ merge_idx,
    const int* __restrict__ seg_ids,
    int N, int P, float* __restrict__ out)
{
    const int j0 = (blockIdx.x * blockDim.x + threadIdx.x) * 2;

    float partial = 0.0f;
    if (j0 + 1 < N) {
        const float* ub0 = U_base + merge_idx[j0];
        const float* ub1 = U_base + merge_idx[j0 + 1];
        const float* uu0 = U + seg_ids[j0];
        const float* uu1 = U + seg_ids[j0 + 1];

        float a0 = 0.f, a1 = 0.f, b0 = 0.f, b1 = 0.f;
        #pragma unroll
        for (int d = 0; d < D_DIM; d += 2) {
            const int oN0 = d * N,       oP0 = d * P;
            const int oN1 = (d + 1) * N, oP1 = (d + 1) * P;
            a0 += ub0[oN0] * uu0[oP0];
            b0 += ub1[oN0] * uu1[oP0];
            a1 += ub0[oN1] * uu0[oP1];
            b1 += ub1[oN1] * uu1[oP1];
        }
        const float d0 = a0 + a1, d1 = b0 + b1;
        partial = -0.5f * (d0 * d0 + d1 * d1);
    } else if (j0 < N) {
        const float* ub = U_base + merge_idx[j0];
        const float* uu = U + seg_ids[j0];
        float a = 0.f;
        #pragma unroll
        for (int d = 0; d < D_DIM; ++d)
            a += ub[d * N] * uu[d * P];
        partial = -0.5f * a * a;
    }

    #pragma unroll
    for (int off = 16; off > 0; off >>= 1)
        partial += __shfl_down_sync(0xffffffffu, partial, off);

    __shared__ float wsum[8];
    const int lane = threadIdx.x & 31, wid = threadIdx.x >> 5;
    if (lane == 0) wsum[wid] = partial;
    __syncthreads();
    if (wid == 0) {
        float v = (lane < 8) ? wsum[lane] : 0.0f;
        #pragma unroll
        for (int off = 4; off > 0; off >>= 1)
            v += __shfl_down_sync(0xffffffffu, v, off);
        if (lane == 0) atomicAdd(out, v);
    }
}

// ---------------------------------------------------------------------------
extern "C" void kernel_launch(void* const* d_in, const int* in_sizes, int n_in,
                              void* d_out, int out_size)
{
    const float* U_base    = (const float*)d_in[0];
    const float* U         = (const float*)d_in[1];
    const int*   merge_idx = (const int*)d_in[2];
    const int*   seg_ids   = (const int*)d_in[3];
    const int*   G         = (const int*)d_in[4];
    float* out = (float*)d_out;

    const int N  = in_sizes[2];                 // 500000
    const int P  = in_sizes[1] / D_DIM;         // 1024
    const int nG = in_sizes[4];                 // P*K = 32768
    const int K  = nG / P;                      // 32

    // 1) M = U U^T (zeroes out[0])
    compute_M_kernel<<<dim3(D_DIM / 32, D_DIM / 32), dim3(32, 32)>>>(U, P, out);
    // 2a) W = M U
    compute_W_kernel<<<dim3(P / 32, D_DIM / 32), dim3(32, 32)>>>(U, P);
    // 2b) rowsq = colsum(W .* U)
    rowsq_reduce_kernel<<<(P + 255) / 256, 256>>>(U, P);
    // 3) gram gather term
    {
        const float coef = -0.5f / ((float)P * (float)K * (float)P);
        gather_kernel<<<32, 256>>>(G, nG, coef, out);
    }
    // 4) main ragged-dot term (HBM-bound)
    {
        const int threads = 256;
        const int jobs = (N + 1) / 2;
        const int blocks = (jobs + threads - 1) / threads;
        dots_kernel<<<blocks, threads>>>(U_base, U, merge_idx, seg_ids, N, P, out);
    }
}

// round 5
// speedup vs baseline: 1.4726x; 1.4293x over previous
#include <cuda_runtime.h>
#include <cuda_bf16.h>

// D=128, N=500000, P=1024, K=32 (index arrays are int32: JAX x64 disabled)
// loss = -0.5 * sum_j dot(U[:,seg_ids[j]], U_base[:,merge_idx[j]])^2
//        -0.5 * mean( (U^T U)[G]^2 )
// Gram: rowsq[r] = u_r^T (U U^T) u_r ;  M = U U^T  (symmetric, 128x128)

#define D_DIM 128
#define P_MAX 4096

__device__ float g_M[D_DIM * D_DIM];     // U U^T (accumulated via atomics; zeroed at end of each call)
__device__ float g_Ut[P_MAX * D_DIM];    // U transposed: g_Ut[c*128 + d] = U[d*P + c]
__device__ float g_rowsq[P_MAX];

// ---------------------------------------------------------------------------
// Kernel 1: per 32-column chunk of U: write transposed copy to g_Ut and
// accumulate M += Uc Uc^T (8x8 register tile per thread, atomic accumulate).
// grid = P/32, block = 256. Also zeroes out[0] (block 0).
// ---------------------------------------------------------------------------
__global__ void __launch_bounds__(256) prep_kernel(const float* __restrict__ U, int P,
                                                   float* __restrict__ out)
{
    __shared__ float Uc[32][132];   // [q][d], pad keeps float4 alignment (132*4=528, %16==0)

    const int q0 = blockIdx.x * 32;
    if (blockIdx.x == 0 && threadIdx.x == 0) out[0] = 0.0f;

    // load chunk: Uc[q][d] = U[d*P + q0+q]
    for (int idx = threadIdx.x; idx < 32 * D_DIM; idx += 256) {
        const int d = idx >> 5;
        const int q = idx & 31;
        Uc[q][d] = U[d * P + q0 + q];
    }
    __syncthreads();

    // write transposed copy (coalesced over d)
    for (int idx = threadIdx.x; idx < 32 * D_DIM; idx += 256) {
        const int q = idx >> 7;
        const int d = idx & 127;
        g_Ut[(q0 + q) * D_DIM + d] = Uc[q][d];
    }

    // M partial: thread -> 8x8 tile at (i0, j0)
    const int i0 = (threadIdx.x >> 4) * 8;
    const int j0 = (threadIdx.x & 15) * 8;
    float acc[8][8];
    #pragma unroll
    for (int i = 0; i < 8; ++i)
        #pragma unroll
        for (int j = 0; j < 8; ++j) acc[i][j] = 0.0f;

    for (int q = 0; q < 32; ++q) {
        float a[8], b[8];
        #pragma unroll
        for (int k = 0; k < 8; ++k) { a[k] = Uc[q][i0 + k]; b[k] = Uc[q][j0 + k]; }
        #pragma unroll
        for (int i = 0; i < 8; ++i)
            #pragma unroll
            for (int j = 0; j < 8; ++j)
                acc[i][j] += a[i] * b[j];
    }

    #pragma unroll
    for (int i = 0; i < 8; ++i)
        #pragma unroll
        for (int j = 0; j < 8; ++j)
            atomicAdd(&g_M[(i0 + i) * D_DIM + (j0 + j)], acc[i][j]);
}

// ---------------------------------------------------------------------------
// Kernel 2: rowsq[c] = u_c^T M u_c.  64 blocks x 256 threads; 16 columns per
// block (2 per warp). M staged through smem in two 64-row halves (symmetric:
// M[d][e] == M[e][d], so row-contiguous reads give the needed column).
// Lane handles d = 4*lane..4*lane+3 via float4.
// ---------------------------------------------------------------------------
__global__ void __launch_bounds__(256) rowsq_kernel(int P)
{
    __shared__ float Ms[64][D_DIM];   // e-half rows
    __shared__ float us[16][D_DIM];   // 16 columns of U (from g_Ut, contiguous)

    const int c0 = blockIdx.x * 16;
    for (int idx = threadIdx.x; idx < 16 * D_DIM; idx += 256)
        us[idx >> 7][idx & 127] = g_Ut[(c0 + (idx >> 7)) * D_DIM + (idx & 127)];

    const int warp = threadIdx.x >> 5;
    const int lane = threadIdx.x & 31;

    float4 t[2];
    t[0] = make_float4(0.f, 0.f, 0.f, 0.f);
    t[1] = make_float4(0.f, 0.f, 0.f, 0.f);

    for (int h = 0; h < 2; ++h) {
        __syncthreads();
        for (int idx = threadIdx.x; idx < 64 * D_DIM; idx += 256)
            Ms[idx >> 7][idx & 127] = g_M[(h * 64 + (idx >> 7)) * D_DIM + (idx & 127)];
        __syncthreads();

        #pragma unroll 2
        for (int cc = 0; cc < 2; ++cc) {
            const int c = warp * 2 + cc;
            #pragma unroll 4
            for (int el = 0; el < 64; ++el) {
                const float ue = us[c][h * 64 + el];
                const float4 m4 = reinterpret_cast<const float4*>(&Ms[el][0])[lane];
                t[cc].x += m4.x * ue;
                t[cc].y += m4.y * ue;
                t[cc].z += m4.z * ue;
                t[cc].w += m4.w * ue;
            }
        }
    }

    #pragma unroll
    for (int cc = 0; cc < 2; ++cc) {
        const int c = warp * 2 + cc;
        const float4 u4 = reinterpret_cast<const float4*>(&us[c][0])[lane];
        float v = t[cc].x * u4.x + t[cc].y * u4.y + t[cc].z * u4.z + t[cc].w * u4.w;
        #pragma unroll
        for (int off = 16; off > 0; off >>= 1)
            v += __shfl_down_sync(0xffffffffu, v, off);
        if (lane == 0) g_rowsq[c0 + c] = v;
    }
}

// ---------------------------------------------------------------------------
// Kernel 3 (dominant): dots + gather fused.
// dots blocks: 4 consecutive columns j per thread. Fast path (contiguous,
// 16B-aligned merge indices + uniform seg in the quad): float4 U_base rows +
// float4 u from g_Ut. Scalar fallback otherwise.
// Last 8 blocks: gram gather term + re-zero g_M for the next graph replay.
// ---------------------------------------------------------------------------
__global__ void __launch_bounds__(256) dots_gather_kernel(
    const float* __restrict__ U_base,
    const int* __restrict__ merge_idx,
    const int* __restrict__ seg_ids,
    const int* __restrict__ G,
    int N, int nG, float coefG, float* __restrict__ out)
{
    const int nDotsBlocks = gridDim.x - 8;
    float partial = 0.0f;

    if ((int)blockIdx.x >= nDotsBlocks) {
        const int gb = blockIdx.x - nDotsBlocks;          // 0..7
        // zero g_M for next replay (g_M already consumed by rowsq_kernel)
        for (int i = gb * 256 + threadIdx.x; i < D_DIM * D_DIM; i += 8 * 256)
            g_M[i] = 0.0f;
        // gather term
        float v = 0.0f;
        for (int i = gb * 256 + threadIdx.x; i < nG; i += 8 * 256)
            v += g_rowsq[G[i]];
        partial = coefG * v;
    } else {
        const int j0 = (blockIdx.x * 256 + threadIdx.x) * 4;
        if (j0 + 3 < N) {
            const int4 mi = *reinterpret_cast<const int4*>(merge_idx + j0);
            const int4 sg = *reinterpret_cast<const int4*>(seg_ids + j0);
            const bool fast = (mi.y == mi.x + 1) & (mi.z == mi.x + 2) &
                              (mi.w == mi.x + 3) & ((mi.x & 3) == 0) &
                              (sg.x == sg.w);
            float a0 = 0.f, a1 = 0.f, a2 = 0.f, a3 = 0.f;
            if (fast) {
                const float* ub = U_base + mi.x;
                const float4* ug = reinterpret_cast<const float4*>(g_Ut + sg.x * D_DIM);
                #pragma unroll 4
                for (int d4 = 0; d4 < D_DIM / 4; ++d4) {
                    const float4 u4 = ug[d4];
                    const int d = d4 * 4;
                    const float4 b0 = *reinterpret_cast<const float4*>(ub + (d + 0) * N);
                    const float4 b1 = *reinterpret_cast<const float4*>(ub + (d + 1) * N);
                    const float4 b2 = *reinterpret_cast<const float4*>(ub + (d + 2) * N);
                    const float4 b3 = *reinterpret_cast<const float4*>(ub + (d + 3) * N);
                    a0 += b0.x * u4.x + b1.x * u4.y + b2.x * u4.z + b3.x * u4.w;
                    a1 += b0.y * u4.x + b1.y * u4.y + b2.y * u4.z + b3.y * u4.w;
                    a2 += b0.z * u4.x + b1.z * u4.y + b2.z * u4.z + b3.z * u4.w;
                    a3 += b0.w * u4.x + b1.w * u4.y + b2.w * u4.z + b3.w * u4.w;
                }
            } else {
                const int mis[4] = {mi.x, mi.y, mi.z, mi.w};
                const int sgs[4] = {sg.x, sg.y, sg.z, sg.w};
                float accs[4] = {0.f, 0.f, 0.f, 0.f};
                #pragma unroll
                for (int k = 0; k < 4; ++k) {
                    const float* ub = U_base + mis[k];
                    const float* u  = g_Ut + sgs[k] * D_DIM;
                    float s = 0.f;
                    #pragma unroll 8
                    for (int d = 0; d < D_DIM; ++d)
                        s += ub[d * N] * u[d];
                    accs[k] = s;
                }
                a0 = accs[0]; a1 = accs[1]; a2 = accs[2]; a3 = accs[3];
            }
            partial = -0.5f * (a0 * a0 + a1 * a1 + a2 * a2 + a3 * a3);
        } else if (j0 < N) {
            float s2 = 0.0f;
            for (int j = j0; j < N; ++j) {
                const float* ub = U_base + merge_idx[j];
                const float* u  = g_Ut + seg_ids[j] * D_DIM;
                float s = 0.f;
                #pragma unroll 8
                for (int d = 0; d < D_DIM; ++d)
                    s += ub[d * N] * u[d];
                s2 += s * s;
            }
            partial = -0.5f * s2;
        }
    }

    // block reduce + one atomic per block
    #pragma unroll
    for (int off = 16; off > 0; off >>= 1)
        partial += __shfl_down_sync(0xffffffffu, partial, off);

    __shared__ float wsum[8];
    const int lane = threadIdx.x & 31, wid = threadIdx.x >> 5;
    if (lane == 0) wsum[wid] = partial;
    __syncthreads();
    if (wid == 0) {
        float v = (lane < 8) ? wsum[lane] : 0.0f;
        #pragma unroll
        for (int off = 4; off > 0; off >>= 1)
            v += __shfl_down_sync(0xffffffffu, v, off);
        if (lane == 0) atomicAdd(out, v);
    }
}

// ---------------------------------------------------------------------------
extern "C" void kernel_launch(void* const* d_in, const int* in_sizes, int n_in,
                              void* d_out, int out_size)
{
    const float* U_base    = (const float*)d_in[0];
    const float* U         = (const float*)d_in[1];
    const int*   merge_idx = (const int*)d_in[2];
    const int*   seg_ids   = (const int*)d_in[3];
    const int*   G         = (const int*)d_in[4];
    float* out = (float*)d_out;

    const int N  = in_sizes[2];                 // 500000
    const int P  = in_sizes[1] / D_DIM;         // 1024
    const int nG = in_sizes[4];                 // P*K = 32768
    const int K  = nG / P;                      // 32

    // 1) transpose U + M = U U^T (atomics; g_M zeroed by previous call's K3 /
    //    static init). Also zeroes out[0].
    prep_kernel<<<P / 32, 256>>>(U, P, out);

    // 2) rowsq[c] = u_c^T M u_c
    rowsq_kernel<<<P / 16, 256>>>(P);

    // 3) dots (+ gather + g_M re-zero), one launch
    {
        const float coefG = -0.5f / ((float)P * (float)K * (float)P);
        const int nDotsBlocks = (N + 1023) / 1024;     // 4 cols/thread, 256 thr
        dots_gather_kernel<<<nDotsBlocks + 8, 256>>>(
            U_base, merge_idx, seg_ids, G, N, nG, coefG, out);
    }
}

// round 6
// speedup vs baseline: 1.6824x; 1.1425x over previous
#include <cuda_runtime.h>
#include <cuda_bf16.h>

// D=128, N=500000, P=1024, K=32 (index arrays are int32: JAX x64 disabled)
// loss = -0.5 * sum_j dot(U[:,seg_ids[j]], U_base[:,merge_idx[j]])^2
//        -0.5 * mean( (U^T U)[G]^2 )
// Gram: rowsq[r] = sum_c S[r,c]^2, S = U^T U. Computed tile-wise, never
// materialized: each 64x64 tile block writes per-col-tile partial row sums.

#define D_DIM 128
#define P_MAX 4096
#define CT_MAX 64            // max P/64 column tiles

__device__ float g_Ut[P_MAX * D_DIM];          // U transposed [P][D]
__device__ float g_rs_part[CT_MAX][P_MAX];     // rowsq partials per column tile

// ---------------------------------------------------------------------------
// Kernel 1 (fused, independent roles):
//   blocks [0, nTrans):        transpose U -> g_Ut (block 0 zeroes out[0])
//   blocks [nTrans, +nGram):   gram tile (rt,ct): S_tile = Ur^T Uc from U
//                              directly; epilogue: g_rs_part[ct][r] = sum_c S^2
// ---------------------------------------------------------------------------
__global__ void __launch_bounds__(256) prep_kernel(const float* __restrict__ U,
                                                   int P, int nTrans,
                                                   float* __restrict__ out)
{
    __shared__ union {
        float T[32][33];
        struct { float A[64][68]; float B[64][68]; } g;   // 64 k-rows x 64(+pad)
    } sm;
    __shared__ float rs[64];

    if (blockIdx.x < (unsigned)nTrans) {
        // ---- transpose role: 32x32 tile ----
        const int nCt32 = P >> 5;
        const int t  = blockIdx.x;
        const int tc = t % nCt32;        // column tile of U
        const int td = t / nCt32;        // row (d) tile
        if (t == 0 && threadIdx.x == 0) out[0] = 0.0f;

        for (int i = threadIdx.x; i < 1024; i += 256) {
            const int dd = i >> 5, cc = i & 31;
            sm.T[dd][cc] = U[(td * 32 + dd) * P + tc * 32 + cc];
        }
        __syncthreads();
        for (int i = threadIdx.x; i < 1024; i += 256) {
            const int cc = i >> 5, dd = i & 31;
            g_Ut[(tc * 32 + cc) * D_DIM + td * 32 + dd] = sm.T[dd][cc];
        }
        return;
    }

    // ---- gram role: 64x64 tile, 4x4 micro-tile per thread ----
    const int bg  = blockIdx.x - nTrans;
    const int nCt = P >> 6;
    const int rt  = bg / nCt, ct = bg % nCt;
    const int r0  = rt * 64,  c0 = ct * 64;
    const int ty  = threadIdx.x >> 4;   // 0..15 -> rows r0+ty*4..
    const int tx  = threadIdx.x & 15;   // 0..15 -> cols c0+tx*4..

    float acc[4][4];
    #pragma unroll
    for (int i = 0; i < 4; ++i)
        #pragma unroll
        for (int j = 0; j < 4; ++j) acc[i][j] = 0.0f;

    for (int kc = 0; kc < D_DIM; kc += 64) {
        __syncthreads();
        for (int i = threadIdx.x; i < 64 * 64; i += 256) {
            const int kk = i >> 6, rr = i & 63;
            sm.g.A[kk][rr] = U[(kc + kk) * P + r0 + rr];
            sm.g.B[kk][rr] = U[(kc + kk) * P + c0 + rr];
        }
        __syncthreads();
        #pragma unroll 8
        for (int kk = 0; kk < 64; ++kk) {
            const float4 a = *reinterpret_cast<const float4*>(&sm.g.A[kk][ty * 4]);
            const float4 b = *reinterpret_cast<const float4*>(&sm.g.B[kk][tx * 4]);
            const float av[4] = {a.x, a.y, a.z, a.w};
            const float bv[4] = {b.x, b.y, b.z, b.w};
            #pragma unroll
            for (int i = 0; i < 4; ++i)
                #pragma unroll
                for (int j = 0; j < 4; ++j)
                    acc[i][j] += av[i] * bv[j];
        }
    }

    // epilogue: per-row sum of squares over this tile's 64 columns
    if (threadIdx.x < 64) rs[threadIdx.x] = 0.0f;
    __syncthreads();
    #pragma unroll
    for (int i = 0; i < 4; ++i) {
        const float s = acc[i][0] * acc[i][0] + acc[i][1] * acc[i][1]
                      + acc[i][2] * acc[i][2] + acc[i][3] * acc[i][3];
        atomicAdd(&rs[ty * 4 + i], s);
    }
    __syncthreads();
    if (threadIdx.x < 64)
        g_rs_part[ct][r0 + threadIdx.x] = rs[threadIdx.x];
}

// ---------------------------------------------------------------------------
// Kernel 2 (dominant): dots + gather fused.
//   dots blocks: 4 consecutive j per thread; float4 fast path when merge
//   indices are contiguous+aligned and seg uniform in the quad.
//   last 16 blocks: gather term, rowsq[idx] = sum_ct g_rs_part[ct][idx].
// ---------------------------------------------------------------------------
__global__ void __launch_bounds__(256) dots_gather_kernel(
    const float* __restrict__ U_base,
    const int* __restrict__ merge_idx,
    const int* __restrict__ seg_ids,
    const int* __restrict__ G,
    int N, int nG, int nCt, float coefG, float* __restrict__ out)
{
    const int nDotsBlocks = gridDim.x - 16;
    float partial = 0.0f;

    if ((int)blockIdx.x >= nDotsBlocks) {
        const int gb = blockIdx.x - nDotsBlocks;          // 0..15
        float v = 0.0f;
        for (int i = gb * 256 + threadIdx.x; i < nG; i += 16 * 256) {
            const int idx = G[i];
            float s = 0.0f;
            #pragma unroll 4
            for (int ctg = 0; ctg < nCt; ++ctg)
                s += g_rs_part[ctg][idx];
            v += s;
        }
        partial = coefG * v;
    } else {
        const int j0 = (blockIdx.x * 256 + threadIdx.x) * 4;
        if (j0 + 3 < N) {
            const int4 mi = *reinterpret_cast<const int4*>(merge_idx + j0);
            const int4 sg = *reinterpret_cast<const int4*>(seg_ids + j0);
            const bool fast = (mi.y == mi.x + 1) & (mi.z == mi.x + 2) &
                              (mi.w == mi.x + 3) & ((mi.x & 3) == 0) &
                              (sg.x == sg.w);
            float a0 = 0.f, a1 = 0.f, a2 = 0.f, a3 = 0.f;
            if (fast) {
                const float* ub = U_base + mi.x;
                const float4* ug = reinterpret_cast<const float4*>(g_Ut + sg.x * D_DIM);
                #pragma unroll 4
                for (int d4 = 0; d4 < D_DIM / 4; ++d4) {
                    const float4 u4 = ug[d4];
                    const int d = d4 * 4;
                    const float4 b0 = *reinterpret_cast<const float4*>(ub + (d + 0) * N);
                    const float4 b1 = *reinterpret_cast<const float4*>(ub + (d + 1) * N);
                    const float4 b2 = *reinterpret_cast<const float4*>(ub + (d + 2) * N);
                    const float4 b3 = *reinterpret_cast<const float4*>(ub + (d + 3) * N);
                    a0 += b0.x * u4.x + b1.x * u4.y + b2.x * u4.z + b3.x * u4.w;
                    a1 += b0.y * u4.x + b1.y * u4.y + b2.y * u4.z + b3.y * u4.w;
                    a2 += b0.z * u4.x + b1.z * u4.y + b2.z * u4.z + b3.z * u4.w;
                    a3 += b0.w * u4.x + b1.w * u4.y + b2.w * u4.z + b3.w * u4.w;
                }
            } else {
                const int mis[4] = {mi.x, mi.y, mi.z, mi.w};
                const int sgs[4] = {sg.x, sg.y, sg.z, sg.w};
                float accs[4] = {0.f, 0.f, 0.f, 0.f};
                #pragma unroll
                for (int k = 0; k < 4; ++k) {
                    const float* ub = U_base + mis[k];
                    const float* u  = g_Ut + sgs[k] * D_DIM;
                    float s = 0.f;
                    #pragma unroll 8
                    for (int d = 0; d < D_DIM; ++d)
                        s += ub[d * N] * u[d];
                    accs[k] = s;
                }
                a0 = accs[0]; a1 = accs[1]; a2 = accs[2]; a3 = accs[3];
            }
            partial = -0.5f * (a0 * a0 + a1 * a1 + a2 * a2 + a3 * a3);
        } else if (j0 < N) {
            float s2 = 0.0f;
            for (int j = j0; j < N; ++j) {
                const float* ub = U_base + merge_idx[j];
                const float* u  = g_Ut + seg_ids[j] * D_DIM;
                float s = 0.f;
                #pragma unroll 8
                for (int d = 0; d < D_DIM; ++d)
                    s += ub[d * N] * u[d];
                s2 += s * s;
            }
            partial = -0.5f * s2;
        }
    }

    // block reduce + one atomic per block
    #pragma unroll
    for (int off = 16; off > 0; off >>= 1)
        partial += __shfl_down_sync(0xffffffffu, partial, off);

    __shared__ float wsum[8];
    const int lane = threadIdx.x & 31, wid = threadIdx.x >> 5;
    if (lane == 0) wsum[wid] = partial;
    __syncthreads();
    if (wid == 0) {
        float v = (lane < 8) ? wsum[lane] : 0.0f;
        #pragma unroll
        for (int off = 4; off > 0; off >>= 1)
            v += __shfl_down_sync(0xffffffffu, v, off);
        if (lane == 0) atomicAdd(out, v);
    }
}

// ---------------------------------------------------------------------------
extern "C" void kernel_launch(void* const* d_in, const int* in_sizes, int n_in,
                              void* d_out, int out_size)
{
    const float* U_base    = (const float*)d_in[0];
    const float* U         = (const float*)d_in[1];
    const int*   merge_idx = (const int*)d_in[2];
    const int*   seg_ids   = (const int*)d_in[3];
    const int*   G         = (const int*)d_in[4];
    float* out = (float*)d_out;

    const int N  = in_sizes[2];                 // 500000
    const int P  = in_sizes[1] / D_DIM;         // 1024
    const int nG = in_sizes[4];                 // P*K = 32768
    const int K  = nG / P;                      // 32
    const int nCt = P / 64;                     // 16

    // 1) transpose (+ zero out) and gram-partial-rowsq, one launch
    {
        const int nTrans = (P / 32) * (D_DIM / 32);   // 128
        const int nGram  = (P / 64) * nCt;            // 256
        prep_kernel<<<nTrans + nGram, 256>>>(U, P, nTrans, out);
    }
    // 2) dots + gather, one launch
    {
        const float coefG = -0.5f / ((float)P * (float)K * (float)P);
        const int nDotsBlocks = (N + 1023) / 1024;    // 4 cols/thread, 256 thr
        dots_gather_kernel<<<nDotsBlocks + 16, 256>>>(
            U_base, merge_idx, seg_ids, G, N, nG, nCt, coefG, out);
    }
}

// round 7
// speedup vs baseline: 1.7597x; 1.0460x over previous
#include <cuda_runtime.h>
#include <cuda_bf16.h>

// D=128, N=500000, P=1024, K=32 (index arrays are int32: JAX x64 disabled)
// loss = -0.5 * sum_j dot(U[:,seg_ids[j]], U_base[:,merge_idx[j]])^2
//        -0.5 * mean( (U^T U)[G]^2 )
// Gram: rowsq[r] = sum_c S[r,c]^2, S = U^T U, computed tile-wise (never
// materialized); each 64x64 tile block writes per-col-tile partial row sums.

#define D_DIM 128
#define P_MAX 4096
#define CT_MAX 64

__device__ float g_rs_part[CT_MAX][P_MAX];   // rowsq partials per column tile

// ---------------------------------------------------------------------------
// Kernel 1: gram tile (rt,ct): S_tile = Ur^T Uc ; epilogue writes
// g_rs_part[ct][r] = sum over this tile's 64 columns of S^2.
// grid = (P/64)^2 = 256, block = 256 (4x4 micro-tile). Block 0 zeroes out[0].
// ---------------------------------------------------------------------------
__global__ void __launch_bounds__(256) gram_kernel(const float* __restrict__ U,
                                                   int P, float* __restrict__ out)
{
    __shared__ float A[64][68];
    __shared__ float B[64][68];
    __shared__ float rs[64];

    if (blockIdx.x == 0 && threadIdx.x == 0) out[0] = 0.0f;

    const int nCt = P >> 6;
    const int rt  = blockIdx.x / nCt, ct = blockIdx.x % nCt;
    const int r0  = rt * 64,  c0 = ct * 64;
    const int ty  = threadIdx.x >> 4;   // 0..15
    const int tx  = threadIdx.x & 15;   // 0..15

    float acc[4][4];
    #pragma unroll
    for (int i = 0; i < 4; ++i)
        #pragma unroll
        for (int j = 0; j < 4; ++j) acc[i][j] = 0.0f;

    for (int kc = 0; kc < D_DIM; kc += 64) {
        __syncthreads();
        for (int i = threadIdx.x; i < 64 * 64; i += 256) {
            const int kk = i >> 6, rr = i & 63;
            A[kk][rr] = U[(kc + kk) * P + r0 + rr];
            B[kk][rr] = U[(kc + kk) * P + c0 + rr];
        }
        __syncthreads();
        #pragma unroll 8
        for (int kk = 0; kk < 64; ++kk) {
            const float4 a = *reinterpret_cast<const float4*>(&A[kk][ty * 4]);
            const float4 b = *reinterpret_cast<const float4*>(&B[kk][tx * 4]);
            const float av[4] = {a.x, a.y, a.z, a.w};
            const float bv[4] = {b.x, b.y, b.z, b.w};
            #pragma unroll
            for (int i = 0; i < 4; ++i)
                #pragma unroll
                for (int j = 0; j < 4; ++j)
                    acc[i][j] += av[i] * bv[j];
        }
    }

    if (threadIdx.x < 64) rs[threadIdx.x] = 0.0f;
    __syncthreads();
    #pragma unroll
    for (int i = 0; i < 4; ++i) {
        const float s = acc[i][0] * acc[i][0] + acc[i][1] * acc[i][1]
                      + acc[i][2] * acc[i][2] + acc[i][3] * acc[i][3];
        atomicAdd(&rs[ty * 4 + i], s);
    }
    __syncthreads();
    if (threadIdx.x < 64)
        g_rs_part[ct][r0 + threadIdx.x] = rs[threadIdx.x];
}

// ---------------------------------------------------------------------------
// Kernel 2 (dominant): dots + gather fused.
//   dots blocks: 2 consecutive j per thread. Fast path (contiguous, even-
//   aligned merge pair + uniform seg + even N): float2 U_base loads, scalar
//   __ldg u loads straight from U (warp-uniform address -> L1 broadcast).
//   last 16 blocks: gather, rowsq[idx] = sum_ct g_rs_part[ct][idx].
// ---------------------------------------------------------------------------
__global__ void __launch_bounds__(256, 6) dots_gather_kernel(
    const float* __restrict__ U_base,
    const float* __restrict__ U,
    const int* __restrict__ merge_idx,
    const int* __restrict__ seg_ids,
    const int* __restrict__ G,
    int N, int P, int nG, int nCt, float coefG, float* __restrict__ out)
{
    const int nDotsBlocks = gridDim.x - 16;
    float partial = 0.0f;

    if ((int)blockIdx.x >= nDotsBlocks) {
        const int gb = blockIdx.x - nDotsBlocks;          // 0..15
        float v = 0.0f;
        for (int i = gb * 256 + threadIdx.x; i < nG; i += 16 * 256) {
            const int idx = G[i];
            float s = 0.0f;
            #pragma unroll 4
            for (int ctg = 0; ctg < nCt; ++ctg)
                s += g_rs_part[ctg][idx];
            v += s;
        }
        partial = coefG * v;
    } else {
        const int j0 = (blockIdx.x * 256 + threadIdx.x) * 2;
        if (j0 + 1 < N) {
            const int2 mi = *reinterpret_cast<const int2*>(merge_idx + j0);
            const int2 sg = *reinterpret_cast<const int2*>(seg_ids + j0);
            const bool fast = (mi.y == mi.x + 1) & ((mi.x & 1) == 0) &
                              (sg.x == sg.y) & ((N & 1) == 0);
            float a0 = 0.f, a1 = 0.f;
            if (fast) {
                const float* ub = U_base + mi.x;
                const float* u  = U + sg.x;
                #pragma unroll 8
                for (int d = 0; d < D_DIM; ++d) {
                    const float2 b = *reinterpret_cast<const float2*>(ub + d * N);
                    const float uv = __ldg(u + d * P);
                    a0 += b.x * uv;
                    a1 += b.y * uv;
                }
            } else {
                const float* ub0 = U_base + mi.x;
                const float* ub1 = U_base + mi.y;
                const float* u0  = U + sg.x;
                const float* u1  = U + sg.y;
                #pragma unroll 8
                for (int d = 0; d < D_DIM; ++d) {
                    a0 += ub0[d * N] * __ldg(u0 + d * P);
                    a1 += ub1[d * N] * __ldg(u1 + d * P);
                }
            }
            partial = -0.5f * (a0 * a0 + a1 * a1);
        } else if (j0 < N) {
            const float* ub = U_base + merge_idx[j0];
            const float* u  = U + seg_ids[j0];
            float a = 0.f;
            #pragma unroll 8
            for (int d = 0; d < D_DIM; ++d)
                a += ub[d * N] * __ldg(u + d * P);
            partial = -0.5f * a * a;
        }
    }

    // block reduce + one atomic per block
    #pragma unroll
    for (int off = 16; off > 0; off >>= 1)
        partial += __shfl_down_sync(0xffffffffu, partial, off);

    __shared__ float wsum[8];
    const int lane = threadIdx.x & 31, wid = threadIdx.x >> 5;
    if (lane == 0) wsum[wid] = partial;
    __syncthreads();
    if (wid == 0) {
        float v = (lane < 8) ? wsum[lane] : 0.0f;
        #pragma unroll
        for (int off = 4; off > 0; off >>= 1)
            v += __shfl_down_sync(0xffffffffu, v, off);
        if (lane == 0) atomicAdd(out, v);
    }
}

// ---------------------------------------------------------------------------
extern "C" void kernel_launch(void* const* d_in, const int* in_sizes, int n_in,
                              void* d_out, int out_size)
{
    const float* U_base    = (const float*)d_in[0];
    const float* U         = (const float*)d_in[1];
    const int*   merge_idx = (const int*)d_in[2];
    const int*   seg_ids   = (const int*)d_in[3];
    const int*   G         = (const int*)d_in[4];
    float* out = (float*)d_out;

    const int N  = in_sizes[2];                 // 500000
    const int P  = in_sizes[1] / D_DIM;         // 1024
    const int nG = in_sizes[4];                 // P*K = 32768
    const int K  = nG / P;                      // 32
    const int nCt = P / 64;                     // 16

    // 1) gram partial row-sums (zeroes out[0] too)
    gram_kernel<<<nCt * nCt, 256>>>(U, P, out);

    // 2) dots (2 j/thread) + gather, one launch
    {
        const float coefG = -0.5f / ((float)P * (float)K * (float)P);
        const int nDotsBlocks = (N / 2 + 255) / 256;   // ~977
        dots_gather_kernel<<<nDotsBlocks + 16, 256>>>(
            U_base, U, merge_idx, seg_ids, G, N, P, nG, nCt, coefG, out);
    }
}